// round 1
// baseline (speedup 1.0000x reference)
#include <cuda_runtime.h>
#include <math.h>

#define N_PROP 1000
#define NUM_CLASSES 81
#define NUM_FG 80
#define SCORE_THRESH 0.05f
#define NMS_THRESH 0.5f
#define DET_PER_IMG 100
#define BBOX_XFORM_CLIP 4.135166556742356f
#define CAND_MAX (N_PROP * NUM_FG)

// ---------- device scratch (no allocations allowed) ----------
__device__ float  g_lse[N_PROP];
__device__ int    g_count;
__device__ float  g_cscore[CAND_MAX];
__device__ float4 g_cbox[CAND_MAX];
__device__ int    g_clabel[CAND_MAX];

// image dims may arrive as int32 or float32 bits; detect robustly.
__device__ __forceinline__ float load_dim(const int* p) {
    int vi = *p;
    if (vi > 0 && vi < 100000) return (float)vi;      // plausible int
    float vf = __int_as_float(vi);                    // else it was a float
    return vf;
}

// ---------- kernel 1: per-proposal log-sum-exp + counter reset ----------
__global__ void lse_kernel(const float* __restrict__ logits) {
    int p = blockIdx.x * blockDim.x + threadIdx.x;
    if (p == 0) g_count = 0;
    if (p >= N_PROP) return;
    const float* row = logits + p * NUM_CLASSES;
    float m = -INFINITY;
    #pragma unroll 1
    for (int c = 0; c < NUM_CLASSES; c++) m = fmaxf(m, row[c]);
    float s = 0.0f;
    #pragma unroll 1
    for (int c = 0; c < NUM_CLASSES; c++) s += expf(row[c] - m);
    g_lse[p] = m + logf(s);
}

// ---------- kernel 2: per-class threshold + decode + sort + NMS ----------
__global__ void nms_kernel(const float* __restrict__ logits,
                           const float* __restrict__ deltas,
                           const float* __restrict__ pboxes,
                           const int* __restrict__ ih_p,
                           const int* __restrict__ iw_p) {
    const int c = blockIdx.x + 1;   // foreground class 1..80
    const int tid = threadIdx.x;
    const int nthr = blockDim.x;

    __shared__ float         s_score[1024];
    __shared__ float4        s_box[1024];
    __shared__ int           s_idx[1024];
    __shared__ unsigned char s_keep[1024];
    __shared__ int           s_cnt;

    if (tid == 0) s_cnt = 0;
    __syncthreads();

    const float W = load_dim(iw_p) - 1.0f;
    const float H = load_dim(ih_p) - 1.0f;

    // threshold + decode + compact
    for (int p = tid; p < N_PROP; p += nthr) {
        float sc = expf(logits[p * NUM_CLASSES + c] - g_lse[p]);
        if (sc > SCORE_THRESH) {
            float x1 = pboxes[p * 4 + 0], y1 = pboxes[p * 4 + 1];
            float x2 = pboxes[p * 4 + 2], y2 = pboxes[p * 4 + 3];
            float w  = x2 - x1 + 1.0f,  h  = y2 - y1 + 1.0f;
            float cx = x1 + 0.5f * w,   cy = y1 + 0.5f * h;
            const float* d = deltas + p * (NUM_CLASSES * 4) + c * 4;
            float dx = d[0] / 10.0f;
            float dy = d[1] / 10.0f;
            float dw = fminf(d[2] / 5.0f, BBOX_XFORM_CLIP);
            float dh = fminf(d[3] / 5.0f, BBOX_XFORM_CLIP);
            float pcx = dx * w + cx, pcy = dy * h + cy;
            float pw  = expf(dw) * w, ph = expf(dh) * h;
            float bx1 = pcx - 0.5f * pw;
            float by1 = pcy - 0.5f * ph;
            float bx2 = pcx + 0.5f * pw - 1.0f;
            float by2 = pcy + 0.5f * ph - 1.0f;
            bx1 = fminf(fmaxf(bx1, 0.0f), W);
            by1 = fminf(fmaxf(by1, 0.0f), H);
            bx2 = fminf(fmaxf(bx2, 0.0f), W);
            by2 = fminf(fmaxf(by2, 0.0f), H);
            int slot = atomicAdd(&s_cnt, 1);
            s_score[slot] = sc;
            s_box[slot]   = make_float4(bx1, by1, bx2, by2);
            s_idx[slot]   = p;
        }
    }
    __syncthreads();
    const int M = s_cnt;
    if (M == 0) return;

    // pad to next pow2 and bitonic sort descending (stable tie-break by idx)
    int P = 1;
    while (P < M) P <<= 1;
    for (int i = M + tid; i < P; i += nthr) {
        s_score[i] = -INFINITY;
        s_idx[i]   = N_PROP + i;
    }
    __syncthreads();

    for (int k = 2; k <= P; k <<= 1) {
        for (int j = k >> 1; j > 0; j >>= 1) {
            for (int i = tid; i < P; i += nthr) {
                int ixj = i ^ j;
                if (ixj > i) {
                    float si = s_score[i], sj = s_score[ixj];
                    int   ii = s_idx[i],   ij = s_idx[ixj];
                    // before_desc(a,b): a precedes b in descending order
                    bool i_first = (si > sj) || (si == sj && ii < ij);
                    bool j_first = (sj > si) || (sj == si && ij < ii);
                    bool desc = ((i & k) == 0);
                    bool do_swap = desc ? j_first : i_first;
                    if (do_swap) {
                        s_score[i] = sj; s_score[ixj] = si;
                        s_idx[i]   = ij; s_idx[ixj]   = ii;
                        float4 tb = s_box[i]; s_box[i] = s_box[ixj]; s_box[ixj] = tb;
                    }
                }
            }
            __syncthreads();
        }
    }

    // greedy NMS: serial outer over kept boxes, parallel inner suppression
    for (int i = tid; i < P; i += nthr) s_keep[i] = (i < M) ? 1 : 0;
    __syncthreads();

    for (int i = 0; i < M - 1; i++) {
        if (s_keep[i]) {   // shared read, uniform across block
            float4 bi = s_box[i];
            float ai = (bi.z - bi.x + 1.0f) * (bi.w - bi.y + 1.0f);
            for (int j = i + 1 + tid; j < M; j += nthr) {
                if (s_keep[j]) {
                    float4 bj = s_box[j];
                    float lx = fmaxf(bi.x, bj.x), ly = fmaxf(bi.y, bj.y);
                    float rx = fminf(bi.z, bj.z), ry = fminf(bi.w, bj.w);
                    float iw = fmaxf(rx - lx + 1.0f, 0.0f);
                    float ih = fmaxf(ry - ly + 1.0f, 0.0f);
                    float inter = iw * ih;
                    float aj = (bj.z - bj.x + 1.0f) * (bj.w - bj.y + 1.0f);
                    float iou = inter / (ai + aj - inter);
                    if (iou > NMS_THRESH) s_keep[j] = 0;
                }
            }
        }
        __syncthreads();
    }

    // append survivors to the global candidate list
    for (int j = tid; j < M; j += nthr) {
        if (s_keep[j]) {
            int pos = atomicAdd(&g_count, 1);
            g_cscore[pos] = s_score[j];
            g_cbox[pos]   = s_box[j];
            g_clabel[pos] = c;
        }
    }
}

// ---------- kernel 3: top-100 by repeated argmax ----------
__global__ void topk_kernel(float* __restrict__ out) {
    __shared__ float r_s[256];
    __shared__ int   r_i[256];
    const int tid = threadIdx.x;
    const int nthr = blockDim.x;
    const int K = g_count;

    for (int r = 0; r < DET_PER_IMG; r++) {
        float bs = -INFINITY;
        int   bi = -1;
        for (int i = tid; i < K; i += nthr) {
            float v = g_cscore[i];
            if (v > bs || (v == bs && bi >= 0 && i < bi)) { bs = v; bi = i; }
        }
        r_s[tid] = bs; r_i[tid] = bi;
        __syncthreads();
        for (int off = nthr >> 1; off > 0; off >>= 1) {
            if (tid < off) {
                float so = r_s[tid + off]; int io = r_i[tid + off];
                if (io >= 0 && (r_i[tid] < 0 || so > r_s[tid] ||
                                (so == r_s[tid] && io < r_i[tid]))) {
                    r_s[tid] = so; r_i[tid] = io;
                }
            }
            __syncthreads();
        }
        if (tid == 0) {
            int idx = r_i[0];
            if (idx >= 0) {
                out[r] = r_s[0];
                float4 b = g_cbox[idx];
                out[DET_PER_IMG + r * 4 + 0] = b.x;
                out[DET_PER_IMG + r * 4 + 1] = b.y;
                out[DET_PER_IMG + r * 4 + 2] = b.z;
                out[DET_PER_IMG + r * 4 + 3] = b.w;
                out[DET_PER_IMG * 5 + r] = (float)g_clabel[idx];
                g_cscore[idx] = -INFINITY;   // remove for next round
            } else {
                out[r] = 0.0f;
                out[DET_PER_IMG + r * 4 + 0] = 0.0f;
                out[DET_PER_IMG + r * 4 + 1] = 0.0f;
                out[DET_PER_IMG + r * 4 + 2] = 0.0f;
                out[DET_PER_IMG + r * 4 + 3] = 0.0f;
                out[DET_PER_IMG * 5 + r] = 0.0f;
            }
        }
        __syncthreads();
    }
}

extern "C" void kernel_launch(void* const* d_in, const int* in_sizes, int n_in,
                              void* d_out, int out_size) {
    const float* logits = (const float*)d_in[0];   // [1000, 81]
    const float* deltas = (const float*)d_in[1];   // [1000, 324]
    const float* pboxes = (const float*)d_in[2];   // [1000, 4]
    const int*   ih     = (const int*)d_in[3];     // scalar
    const int*   iw     = (const int*)d_in[4];     // scalar

    lse_kernel<<<(N_PROP + 255) / 256, 256>>>(logits);
    nms_kernel<<<NUM_FG, 256>>>(logits, deltas, pboxes, ih, iw);
    topk_kernel<<<1, 256>>>((float*)d_out);
}

// round 2
// speedup vs baseline: 1.9694x; 1.9694x over previous
#include <cuda_runtime.h>
#include <math.h>

#define N_PROP 1000
#define NUM_CLASSES 81
#define NUM_FG 80
#define SCORE_THRESH 0.05f
#define NMS_THRESH 0.5f
#define DET_PER_IMG 100
#define BBOX_XFORM_CLIP 4.135166556742356f
#define CAND_MAX (N_PROP * NUM_FG)
#define TOPK_SHMAX 16384   // max K for shared-sort path (128KB dyn smem)

typedef unsigned long long u64;
typedef unsigned int u32;

// ---------- device scratch (no allocations allowed) ----------
__device__ float  g_lse[N_PROP];
__device__ int    g_count;
__device__ float  g_cscore[CAND_MAX];   // compact candidate scores
__device__ int    g_ckey[CAND_MAX];     // compact candidate flat keys
__device__ float4 g_boxkey[CAND_MAX];   // boxes addressed by flat key (deterministic)

// image dims may arrive as int32 or float32 bits; detect robustly.
__device__ __forceinline__ float load_dim(const int* p) {
    int vi = *p;
    if (vi > 0 && vi < 100000) return (float)vi;
    return __int_as_float(vi);
}

// ---------- kernel 1: warp-per-proposal log-sum-exp ----------
__global__ void lse_kernel(const float* __restrict__ logits) {
    const int lane = threadIdx.x & 31;
    const int p = blockIdx.x * (blockDim.x >> 5) + (threadIdx.x >> 5);
    if (blockIdx.x == 0 && threadIdx.x == 0) g_count = 0;
    if (p >= N_PROP) return;
    const float* row = logits + p * NUM_CLASSES;

    float m = -INFINITY;
    float v0 = row[lane];
    float v1 = row[lane + 32];
    float v2 = (lane + 64 < NUM_CLASSES) ? row[lane + 64] : -INFINITY;
    m = fmaxf(fmaxf(v0, v1), v2);
    #pragma unroll
    for (int o = 16; o > 0; o >>= 1) m = fmaxf(m, __shfl_xor_sync(0xffffffffu, m, o));

    float s = expf(v0 - m) + expf(v1 - m);
    if (lane + 64 < NUM_CLASSES) s += expf(v2 - m);
    #pragma unroll
    for (int o = 16; o > 0; o >>= 1) s += __shfl_xor_sync(0xffffffffu, s, o);

    if (lane == 0) g_lse[p] = m + logf(s);
}

// ---------- kernel 2: per-class threshold + decode + sort + NMS ----------
__global__ void nms_kernel(const float* __restrict__ logits,
                           const float* __restrict__ deltas,
                           const float* __restrict__ pboxes,
                           const int* __restrict__ ih_p,
                           const int* __restrict__ iw_p) {
    const int c = blockIdx.x + 1;   // foreground class 1..80
    const int tid = threadIdx.x;
    const int nthr = blockDim.x;

    __shared__ float         s_score[1024];
    __shared__ float4        s_box[1024];
    __shared__ int           s_idx[1024];
    __shared__ unsigned char s_keep[1024];
    __shared__ int           s_cnt;

    if (tid == 0) s_cnt = 0;
    __syncthreads();

    const float W = load_dim(iw_p) - 1.0f;
    const float H = load_dim(ih_p) - 1.0f;

    // threshold + decode + compact
    for (int p = tid; p < N_PROP; p += nthr) {
        float sc = expf(logits[p * NUM_CLASSES + c] - g_lse[p]);
        if (sc > SCORE_THRESH) {
            float x1 = pboxes[p * 4 + 0], y1 = pboxes[p * 4 + 1];
            float x2 = pboxes[p * 4 + 2], y2 = pboxes[p * 4 + 3];
            float w  = x2 - x1 + 1.0f,  h  = y2 - y1 + 1.0f;
            float cx = x1 + 0.5f * w,   cy = y1 + 0.5f * h;
            const float* d = deltas + p * (NUM_CLASSES * 4) + c * 4;
            float dx = d[0] / 10.0f;
            float dy = d[1] / 10.0f;
            float dw = fminf(d[2] / 5.0f, BBOX_XFORM_CLIP);
            float dh = fminf(d[3] / 5.0f, BBOX_XFORM_CLIP);
            float pcx = dx * w + cx, pcy = dy * h + cy;
            float pw  = expf(dw) * w, ph = expf(dh) * h;
            float bx1 = fminf(fmaxf(pcx - 0.5f * pw, 0.0f), W);
            float by1 = fminf(fmaxf(pcy - 0.5f * ph, 0.0f), H);
            float bx2 = fminf(fmaxf(pcx + 0.5f * pw - 1.0f, 0.0f), W);
            float by2 = fminf(fmaxf(pcy + 0.5f * ph - 1.0f, 0.0f), H);
            int slot = atomicAdd(&s_cnt, 1);
            s_score[slot] = sc;
            s_box[slot]   = make_float4(bx1, by1, bx2, by2);
            s_idx[slot]   = p;
        }
    }
    __syncthreads();
    const int M = s_cnt;
    if (M == 0) return;

    // pad to next pow2 and bitonic sort descending (stable tie-break by idx)
    int P = 1;
    while (P < M) P <<= 1;
    for (int i = M + tid; i < P; i += nthr) {
        s_score[i] = -INFINITY;
        s_idx[i]   = N_PROP + i;
    }
    __syncthreads();

    for (int k = 2; k <= P; k <<= 1) {
        for (int j = k >> 1; j > 0; j >>= 1) {
            for (int i = tid; i < P; i += nthr) {
                int ixj = i ^ j;
                if (ixj > i) {
                    float si = s_score[i], sj = s_score[ixj];
                    int   ii = s_idx[i],   ij = s_idx[ixj];
                    bool i_first = (si > sj) || (si == sj && ii < ij);
                    bool j_first = (sj > si) || (sj == si && ij < ii);
                    bool desc = ((i & k) == 0);
                    bool do_swap = desc ? j_first : i_first;
                    if (do_swap) {
                        s_score[i] = sj; s_score[ixj] = si;
                        s_idx[i]   = ij; s_idx[ixj]   = ii;
                        float4 tb = s_box[i]; s_box[i] = s_box[ixj]; s_box[ixj] = tb;
                    }
                }
            }
            __syncthreads();
        }
    }

    // greedy NMS: serial outer over kept boxes, parallel inner suppression
    for (int i = tid; i < P; i += nthr) s_keep[i] = (i < M) ? 1 : 0;
    __syncthreads();

    for (int i = 0; i < M - 1; i++) {
        if (s_keep[i]) {
            float4 bi = s_box[i];
            float ai = (bi.z - bi.x + 1.0f) * (bi.w - bi.y + 1.0f);
            for (int j = i + 1 + tid; j < M; j += nthr) {
                if (s_keep[j]) {
                    float4 bj = s_box[j];
                    float lx = fmaxf(bi.x, bj.x), ly = fmaxf(bi.y, bj.y);
                    float rx = fminf(bi.z, bj.z), ry = fminf(bi.w, bj.w);
                    float iw = fmaxf(rx - lx + 1.0f, 0.0f);
                    float ih = fmaxf(ry - ly + 1.0f, 0.0f);
                    float inter = iw * ih;
                    float aj = (bj.z - bj.x + 1.0f) * (bj.w - bj.y + 1.0f);
                    float iou = inter / (ai + aj - inter);
                    if (iou > NMS_THRESH) s_keep[j] = 0;
                }
            }
        }
        __syncthreads();
    }

    // append survivors: compact (score,key) list + box at deterministic key slot
    for (int j = tid; j < M; j += nthr) {
        if (s_keep[j]) {
            int key = (c - 1) * N_PROP + j;     // reference flat index
            int pos = atomicAdd(&g_count, 1);
            g_cscore[pos] = s_score[j];
            g_ckey[pos]   = key;
            g_boxkey[key] = s_box[j];
        }
    }
}

// ---------- kernel 3: top-100 via one bitonic sort of packed u64 keys ----------
__global__ void topk_kernel(float* __restrict__ out) {
    extern __shared__ u64 sh[];
    const int tid = threadIdx.x;
    const int nthr = blockDim.x;
    const int K = g_count;

    if (K <= TOPK_SHMAX) {
        int P2 = 2048;                 // keep all threads busy; K rarely below this
        while (P2 < K) P2 <<= 1;

        for (int i = tid; i < P2; i += nthr) {
            if (i < K) {
                u32 sb = __float_as_uint(g_cscore[i]);   // scores > 0 -> monotonic bits
                sh[i] = ((u64)sb << 32) | (u32)(~g_ckey[i]);
            } else {
                sh[i] = 0ULL;
            }
        }
        __syncthreads();

        // bitonic sort, descending
        for (int k = 2; k <= P2; k <<= 1) {
            for (int j = k >> 1; j > 0; j >>= 1) {
                for (int i = tid; i < P2; i += nthr) {
                    int ixj = i ^ j;
                    if (ixj > i) {
                        u64 a = sh[i], b = sh[ixj];
                        bool up = ((i & k) == 0);        // descending segments
                        if (up ? (a < b) : (a > b)) { sh[i] = b; sh[ixj] = a; }
                    }
                }
                __syncthreads();
            }
        }

        for (int r = tid; r < DET_PER_IMG; r += nthr) {
            if (r < K) {
                u64 v = sh[r];
                float sc = __uint_as_float((u32)(v >> 32));
                int key = (int)(~(u32)v);
                float4 b = g_boxkey[key];
                out[r] = sc;
                out[DET_PER_IMG + r * 4 + 0] = b.x;
                out[DET_PER_IMG + r * 4 + 1] = b.y;
                out[DET_PER_IMG + r * 4 + 2] = b.z;
                out[DET_PER_IMG + r * 4 + 3] = b.w;
                out[DET_PER_IMG * 5 + r] = (float)(key / N_PROP + 1);
            } else {
                out[r] = 0.0f;
                out[DET_PER_IMG + r * 4 + 0] = 0.0f;
                out[DET_PER_IMG + r * 4 + 1] = 0.0f;
                out[DET_PER_IMG + r * 4 + 2] = 0.0f;
                out[DET_PER_IMG + r * 4 + 3] = 0.0f;
                out[DET_PER_IMG * 5 + r] = 0.0f;
            }
        }
        return;
    }

    // -------- fallback: K > TOPK_SHMAX (never exhausts: K > 100) --------
    __shared__ u64 r_v[1024];
    __shared__ int r_i[1024];
    for (int r = 0; r < DET_PER_IMG; r++) {
        u64 bv = 0ULL; int bi = -1;
        for (int i = tid; i < K; i += nthr) {
            u32 sb = __float_as_uint(g_cscore[i]);       // invalidated -> 0.0f, stays >= 0
            u64 v = ((u64)sb << 32) | (u32)(~g_ckey[i]);
            if (v > bv) { bv = v; bi = i; }
        }
        r_v[tid] = bv; r_i[tid] = bi;
        __syncthreads();
        for (int off = nthr >> 1; off > 0; off >>= 1) {
            if (tid < off) {
                if (r_v[tid + off] > r_v[tid]) { r_v[tid] = r_v[tid + off]; r_i[tid] = r_i[tid + off]; }
            }
            __syncthreads();
        }
        if (tid == 0) {
            int idx = r_i[0];
            u64 v = r_v[0];
            float sc = __uint_as_float((u32)(v >> 32));
            int key = (int)(~(u32)v);
            float4 b = g_boxkey[key];
            out[r] = sc;
            out[DET_PER_IMG + r * 4 + 0] = b.x;
            out[DET_PER_IMG + r * 4 + 1] = b.y;
            out[DET_PER_IMG + r * 4 + 2] = b.z;
            out[DET_PER_IMG + r * 4 + 3] = b.w;
            out[DET_PER_IMG * 5 + r] = (float)(key / N_PROP + 1);
            g_cscore[idx] = 0.0f;   // remove for next round (stays in positive domain)
        }
        __syncthreads();
    }
}

extern "C" void kernel_launch(void* const* d_in, const int* in_sizes, int n_in,
                              void* d_out, int out_size) {
    const float* logits = (const float*)d_in[0];   // [1000, 81]
    const float* deltas = (const float*)d_in[1];   // [1000, 324]
    const float* pboxes = (const float*)d_in[2];   // [1000, 4]
    const int*   ih     = (const int*)d_in[3];     // scalar
    const int*   iw     = (const int*)d_in[4];     // scalar

    static bool attr_done = false;   // idempotent host-side attribute opt-in
    if (!attr_done) {
        cudaFuncSetAttribute(topk_kernel, cudaFuncAttributeMaxDynamicSharedMemorySize,
                             TOPK_SHMAX * sizeof(u64));
        attr_done = true;
    }

    lse_kernel<<<(N_PROP * 32 + 255) / 256, 256>>>(logits);
    nms_kernel<<<NUM_FG, 256>>>(logits, deltas, pboxes, ih, iw);
    topk_kernel<<<1, 1024, TOPK_SHMAX * sizeof(u64)>>>((float*)d_out);
}

// round 5
// speedup vs baseline: 4.9230x; 2.4997x over previous
#include <cuda_runtime.h>
#include <math.h>

#define N_PROP 1000
#define NUM_CLASSES 81
#define NUM_FG 80
#define SCORE_THRESH 0.05f
#define NMS_THRESH 0.5f
#define DET_PER_IMG 100
#define BBOX_XFORM_CLIP 4.135166556742356f
#define CAND_MAX (N_PROP * NUM_FG)

#define MROW 1024           // mask rows (M <= N_PROP = 1000 always fits)
#define MWORDS 32           // 1024 bits
#define NBINS 4096
#define TOPK_CAP 2048
#define TOPK_THREADS 512

typedef unsigned long long u64;
typedef unsigned int u32;

// ---------- device scratch (no allocations allowed) ----------
__device__ float  g_lse[N_PROP];
__device__ int    g_count;
__device__ float  g_cscore[CAND_MAX];   // compact candidate scores
__device__ int    g_ckey[CAND_MAX];     // compact candidate flat keys
__device__ float4 g_boxkey[CAND_MAX];   // boxes addressed by flat key (deterministic)
__device__ u32    g_mask[NUM_FG * MROW * MWORDS];   // per-class suppression bits

__device__ __forceinline__ float load_dim(const int* p) {
    int vi = *p;
    if (vi > 0 && vi < 100000) return (float)vi;
    return __int_as_float(vi);
}

// ---------- kernel 1: warp-per-proposal log-sum-exp ----------
__global__ void lse_kernel(const float* __restrict__ logits) {
    const int lane = threadIdx.x & 31;
    const int p = blockIdx.x * (blockDim.x >> 5) + (threadIdx.x >> 5);
    if (blockIdx.x == 0 && threadIdx.x == 0) g_count = 0;
    if (p >= N_PROP) return;
    const float* row = logits + p * NUM_CLASSES;

    float v0 = row[lane];
    float v1 = row[lane + 32];
    float v2 = (lane + 64 < NUM_CLASSES) ? row[lane + 64] : -INFINITY;
    float m = fmaxf(fmaxf(v0, v1), v2);
    #pragma unroll
    for (int o = 16; o > 0; o >>= 1) m = fmaxf(m, __shfl_xor_sync(0xffffffffu, m, o));

    float s = expf(v0 - m) + expf(v1 - m);
    if (lane + 64 < NUM_CLASSES) s += expf(v2 - m);
    #pragma unroll
    for (int o = 16; o > 0; o >>= 1) s += __shfl_xor_sync(0xffffffffu, s, o);

    if (lane == 0) g_lse[p] = m + logf(s);
}

// ---------- kernel 2: per-class threshold + decode + sort + bitmask NMS ----------
__global__ void nms_kernel(const float* __restrict__ logits,
                           const float* __restrict__ deltas,
                           const float* __restrict__ pboxes,
                           const int* __restrict__ ih_p,
                           const int* __restrict__ iw_p) {
    const int c = blockIdx.x + 1;            // foreground class 1..80
    const int tid = threadIdx.x;
    const int nthr = blockDim.x;

    __shared__ u64    s_key[1024];           // (score_bits<<32) | ~prop_idx
    __shared__ float4 s_box[1024];
    __shared__ u32    s_keepw[MWORDS];
    __shared__ int    s_cnt;

    if (tid == 0) s_cnt = 0;
    __syncthreads();

    const float W = load_dim(iw_p) - 1.0f;
    const float H = load_dim(ih_p) - 1.0f;

    // threshold + decode + compact
    for (int p = tid; p < N_PROP; p += nthr) {
        float sc = expf(logits[p * NUM_CLASSES + c] - g_lse[p]);
        if (sc > SCORE_THRESH) {
            float x1 = pboxes[p * 4 + 0], y1 = pboxes[p * 4 + 1];
            float x2 = pboxes[p * 4 + 2], y2 = pboxes[p * 4 + 3];
            float w  = x2 - x1 + 1.0f,  h  = y2 - y1 + 1.0f;
            float cx = x1 + 0.5f * w,   cy = y1 + 0.5f * h;
            const float* d = deltas + p * (NUM_CLASSES * 4) + c * 4;
            float dx = d[0] / 10.0f;
            float dy = d[1] / 10.0f;
            float dw = fminf(d[2] / 5.0f, BBOX_XFORM_CLIP);
            float dh = fminf(d[3] / 5.0f, BBOX_XFORM_CLIP);
            float pcx = dx * w + cx, pcy = dy * h + cy;
            float pw  = expf(dw) * w, ph = expf(dh) * h;
            float bx1 = fminf(fmaxf(pcx - 0.5f * pw, 0.0f), W);
            float by1 = fminf(fmaxf(pcy - 0.5f * ph, 0.0f), H);
            float bx2 = fminf(fmaxf(pcx + 0.5f * pw - 1.0f, 0.0f), W);
            float by2 = fminf(fmaxf(pcy + 0.5f * ph - 1.0f, 0.0f), H);
            int slot = atomicAdd(&s_cnt, 1);
            s_key[slot] = ((u64)__float_as_uint(sc) << 32) | (u32)(~p);
            s_box[slot] = make_float4(bx1, by1, bx2, by2);
        }
    }
    __syncthreads();
    const int M = s_cnt;
    if (M == 0) return;

    // pad to pow2, bitonic sort descending on packed u64 (ties -> smaller p first)
    int P = 1;
    while (P < M) P <<= 1;
    for (int i = M + tid; i < P; i += nthr) s_key[i] = 0ULL;
    __syncthreads();

    for (int k = 2; k <= P; k <<= 1) {
        for (int j = k >> 1; j > 0; j >>= 1) {
            for (int i = tid; i < P; i += nthr) {
                int ixj = i ^ j;
                if (ixj > i) {
                    u64 a = s_key[i], b = s_key[ixj];
                    bool up = ((i & k) == 0);        // descending segments
                    if (up ? (a < b) : (a > b)) {
                        s_key[i] = b; s_key[ixj] = a;
                        float4 tb = s_box[i]; s_box[i] = s_box[ixj]; s_box[ixj] = tb;
                    }
                }
            }
            __syncthreads();
        }
    }

    // build suppression bitmask rows in parallel (row i: bits j>i with IoU>thresh)
    u32* mask = &g_mask[(c - 1) * MROW * MWORDS];
    const int Wd = (M + 31) >> 5;
    for (int i = tid; i < M; i += nthr) {
        u32* row = &mask[i * MWORDS];
        #pragma unroll 4
        for (int w = 0; w < Wd; w++) row[w] = 0;
        float4 bi = s_box[i];
        float ai = (bi.z - bi.x + 1.0f) * (bi.w - bi.y + 1.0f);
        u32 cur = 0; int curw = (i + 1) >> 5;
        for (int j = i + 1; j < M; j++) {
            int w = j >> 5;
            if (w != curw) {
                if (cur) row[curw] = cur;
                cur = 0; curw = w;
            }
            float4 bj = s_box[j];
            float lx = fmaxf(bi.x, bj.x), ly = fmaxf(bi.y, bj.y);
            float rx = fminf(bi.z, bj.z), ry = fminf(bi.w, bj.w);
            float iw = fmaxf(rx - lx + 1.0f, 0.0f);
            float ih = fmaxf(ry - ly + 1.0f, 0.0f);
            float inter = iw * ih;
            float aj = (bj.z - bj.x + 1.0f) * (bj.w - bj.y + 1.0f);
            if (inter / (ai + aj - inter) > NMS_THRESH) cur |= 1u << (j & 31);
        }
        if (cur) row[curw] = cur;
    }
    __syncthreads();

    // barrier-free greedy resolution over bit words (thread 0)
    if (tid == 0) {
        u32 kw[MWORDS];
        for (int w = 0; w < Wd; w++) kw[w] = 0xffffffffu;
        int rem = M & 31;
        if (rem) kw[Wd - 1] = (1u << rem) - 1u;
        for (int i = 0; i < M; i++) {
            if ((kw[i >> 5] >> (i & 31)) & 1u) {
                const u32* row = &mask[i * MWORDS];
                for (int w = 0; w < Wd; w++) kw[w] &= ~row[w];
            }
        }
        for (int w = 0; w < Wd; w++) s_keepw[w] = kw[w];
    }
    __syncthreads();

    // append survivors: compact (score,key) list + box at deterministic key slot
    for (int j = tid; j < M; j += nthr) {
        if ((s_keepw[j >> 5] >> (j & 31)) & 1u) {
            int key = (c - 1) * N_PROP + j;     // reference flat index (sorted position)
            int pos = atomicAdd(&g_count, 1);
            g_cscore[pos] = __uint_as_float((u32)(s_key[j] >> 32));
            g_ckey[pos]   = key;
            g_boxkey[key] = s_box[j];
        }
    }
}

// ---------- kernel 3: histogram select + tiny bitonic sort ----------
__device__ __forceinline__ int score_bin(u32 bits) {
    int b = (int)(bits >> 14) - 0xF400;      // scores in (0.05, 1] -> [0x133, 0xA00]
    return min(NBINS - 1, max(0, b));
}

__global__ void __launch_bounds__(TOPK_THREADS) topk_kernel(float* __restrict__ out) {
    __shared__ u64 s_buf[TOPK_CAP];          // 16KB (fallback aliases this)
    __shared__ int hist[NBINS];              // 16KB
    __shared__ int s_part[TOPK_THREADS];     // 2KB
    __shared__ int s_bstar;
    __shared__ int s_cnt;

    const int tid = threadIdx.x;
    const int nthr = blockDim.x;             // 512
    const int K = g_count;
    const int target = (K < DET_PER_IMG) ? K : DET_PER_IMG;

    for (int i = tid; i < NBINS; i += nthr) hist[i] = 0;
    if (tid == 0) { s_bstar = 0; s_cnt = 0; }
    __syncthreads();

    for (int i = tid; i < K; i += nthr)
        atomicAdd(&hist[score_bin(__float_as_uint(g_cscore[i]))], 1);
    __syncthreads();

    // suffix scan over 512 chunks of 8 bins
    const int CH = NBINS / TOPK_THREADS;     // 8
    const int base = tid * CH;
    int cs[8];
    int sum = 0;
    #pragma unroll
    for (int t = 0; t < CH; t++) { cs[t] = hist[base + t]; sum += cs[t]; }
    s_part[tid] = sum;
    __syncthreads();
    for (int off = 1; off < TOPK_THREADS; off <<= 1) {
        int add = (tid + off < TOPK_THREADS) ? s_part[tid + off] : 0;
        __syncthreads();
        s_part[tid] += add;
        __syncthreads();
    }
    // b* = largest bin with suffix count >= target
    {
        int suf = (tid < TOPK_THREADS - 1) ? s_part[tid + 1] : 0;
        #pragma unroll
        for (int t = CH - 1; t >= 0; t--) {
            suf += cs[t];
            if (suf >= target) { atomicMax(&s_bstar, base + t); break; }
        }
    }
    __syncthreads();
    const int bstar = s_bstar;

    // compact candidates in bins >= b*
    for (int i = tid; i < K; i += nthr) {
        u32 sb = __float_as_uint(g_cscore[i]);
        if (score_bin(sb) >= bstar) {
            int pos = atomicAdd(&s_cnt, 1);
            if (pos < TOPK_CAP)
                s_buf[pos] = ((u64)sb << 32) | (u32)(~g_ckey[i]);
        }
    }
    __syncthreads();
    const int C = s_cnt;

    if (C <= TOPK_CAP) {
        int P2 = 128;
        while (P2 < C) P2 <<= 1;
        for (int i = C + tid; i < P2; i += nthr) s_buf[i] = 0ULL;
        __syncthreads();

        for (int k = 2; k <= P2; k <<= 1) {
            for (int j = k >> 1; j > 0; j >>= 1) {
                for (int i = tid; i < P2; i += nthr) {
                    int ixj = i ^ j;
                    if (ixj > i) {
                        u64 a = s_buf[i], b = s_buf[ixj];
                        bool up = ((i & k) == 0);
                        if (up ? (a < b) : (a > b)) { s_buf[i] = b; s_buf[ixj] = a; }
                    }
                }
                __syncthreads();
            }
        }

        for (int r = tid; r < DET_PER_IMG; r += nthr) {
            if (r < C) {
                u64 v = s_buf[r];
                int key = (int)(~(u32)v);
                float4 b = g_boxkey[key];
                out[r] = __uint_as_float((u32)(v >> 32));
                out[DET_PER_IMG + r * 4 + 0] = b.x;
                out[DET_PER_IMG + r * 4 + 1] = b.y;
                out[DET_PER_IMG + r * 4 + 2] = b.z;
                out[DET_PER_IMG + r * 4 + 3] = b.w;
                out[DET_PER_IMG * 5 + r] = (float)(key / N_PROP + 1);
            } else {
                out[r] = 0.0f;
                out[DET_PER_IMG + r * 4 + 0] = 0.0f;
                out[DET_PER_IMG + r * 4 + 1] = 0.0f;
                out[DET_PER_IMG + r * 4 + 2] = 0.0f;
                out[DET_PER_IMG + r * 4 + 3] = 0.0f;
                out[DET_PER_IMG * 5 + r] = 0.0f;
            }
        }
        return;
    }

    // -------- fallback: repeated global argmax (C > TOPK_CAP, pathological) ------
    // aliases s_buf: r_v = s_buf[0..nthr), r_i = ints after that
    u64* r_v = s_buf;
    int* r_i = (int*)(s_buf + TOPK_THREADS);
    __syncthreads();
    for (int r = 0; r < DET_PER_IMG; r++) {
        u64 bv = 0ULL; int bi = -1;
        for (int i = tid; i < K; i += nthr) {
            u32 sb = __float_as_uint(g_cscore[i]);
            u64 v = ((u64)sb << 32) | (u32)(~g_ckey[i]);
            if (v > bv) { bv = v; bi = i; }
        }
        r_v[tid] = bv; r_i[tid] = bi;
        __syncthreads();
        for (int off = nthr >> 1; off > 0; off >>= 1) {
            if (tid < off) {
                if (r_v[tid + off] > r_v[tid]) { r_v[tid] = r_v[tid + off]; r_i[tid] = r_i[tid + off]; }
            }
            __syncthreads();
        }
        if (tid == 0) {
            int idx = r_i[0];
            u64 v = r_v[0];
            int key = (int)(~(u32)v);
            float4 b = g_boxkey[key];
            out[r] = __uint_as_float((u32)(v >> 32));
            out[DET_PER_IMG + r * 4 + 0] = b.x;
            out[DET_PER_IMG + r * 4 + 1] = b.y;
            out[DET_PER_IMG + r * 4 + 2] = b.z;
            out[DET_PER_IMG + r * 4 + 3] = b.w;
            out[DET_PER_IMG * 5 + r] = (float)(key / N_PROP + 1);
            g_cscore[idx] = 0.0f;
        }
        __syncthreads();
    }
}

extern "C" void kernel_launch(void* const* d_in, const int* in_sizes, int n_in,
                              void* d_out, int out_size) {
    const float* logits = (const float*)d_in[0];   // [1000, 81]
    const float* deltas = (const float*)d_in[1];   // [1000, 324]
    const float* pboxes = (const float*)d_in[2];   // [1000, 4]
    const int*   ih     = (const int*)d_in[3];     // scalar
    const int*   iw     = (const int*)d_in[4];     // scalar

    lse_kernel<<<(N_PROP * 32 + 255) / 256, 256>>>(logits);
    nms_kernel<<<NUM_FG, 256>>>(logits, deltas, pboxes, ih, iw);
    topk_kernel<<<1, TOPK_THREADS>>>((float*)d_out);
}

// round 7
// speedup vs baseline: 5.5551x; 1.1284x over previous
#include <cuda_runtime.h>
#include <math.h>

#define N_PROP 1000
#define NUM_CLASSES 81
#define NUM_FG 80
#define SCORE_THRESH 0.05f
#define NMS_THRESH 0.5f
#define DET_PER_IMG 100
#define BBOX_XFORM_CLIP 4.135166556742356f
#define CAND_MAX (N_PROP * NUM_FG)

#define NBLOCKS 80
#define NTHREADS 256

#define MROW 1024            // global-mask rows (fallback, M <= 1000)
#define MWORDS 32            // 1024 bits
#define MROW_SH 256          // shared-mask rows (fast path)
#define MWORDS_SH 8          // 256 bits

#define NBINS 4096
#define TOPK_CAP 2048

typedef unsigned long long u64;
typedef unsigned int u32;

// ---------- device scratch (no allocations allowed) ----------
__device__ float  g_lse[N_PROP];
__device__ int    g_count;
__device__ float  g_cscore[CAND_MAX];
__device__ int    g_ckey[CAND_MAX];
__device__ float4 g_boxkey[CAND_MAX];
__device__ u32    g_mask[NUM_FG * MROW * MWORDS];   // fallback mask (M > 256)

// self-resetting grid barrier state (gen is monotonic across graph replays)
__device__ unsigned int g_bar_count = 0;
__device__ unsigned int g_bar_gen   = 0;

__device__ __forceinline__ void grid_sync() {
    __threadfence();
    __syncthreads();
    if (threadIdx.x == 0) {
        unsigned gen = *((volatile unsigned*)&g_bar_gen);
        unsigned old = atomicInc(&g_bar_count, NBLOCKS - 1);   // wraps to 0 -> self-reset
        if (old == NBLOCKS - 1) {
            atomicAdd(&g_bar_gen, 1);
        } else {
            while (*((volatile unsigned*)&g_bar_gen) == gen) { __nanosleep(32); }
        }
    }
    __syncthreads();
    __threadfence();
}

__device__ __forceinline__ float load_dim(const int* p) {
    int vi = *p;
    if (vi > 0 && vi < 100000) return (float)vi;
    return __int_as_float(vi);
}

__device__ __forceinline__ int score_bin(u32 bits) {
    int b = (int)(bits >> 14) - 0xF400;      // scores in (0.05, 1] -> positive bins
    return min(NBINS - 1, max(0, b));
}

// ---------- shared memory union across phases ----------
struct SmemNMS {
    u64    key[1024];        // (score_bits<<32) | ~prop_idx
    float4 box[1024];
    u32    masksh[MROW_SH * MWORDS_SH];
    u32    keepw[MWORDS];
    int    cnt;
};
struct SmemTopk {
    u64 buf[TOPK_CAP];
    int hist[NBINS];
    int part[NTHREADS];
    int bstar;
    int cnt;
};
union SmemAll {
    SmemNMS  nms;
    SmemTopk topk;
};

__global__ void __launch_bounds__(NTHREADS, 1)
fused_kernel(const float* __restrict__ logits,
             const float* __restrict__ deltas,
             const float* __restrict__ pboxes,
             const int* __restrict__ ih_p,
             const int* __restrict__ iw_p,
             float* __restrict__ out) {
    __shared__ SmemAll sm;
    const int tid  = threadIdx.x;
    const int bid  = blockIdx.x;
    const int lane = tid & 31;
    const int wid  = tid >> 5;

    // ================= Phase A: log-sum-exp (warp per proposal) =================
    if (bid == 0 && tid == 0) g_count = 0;
    {
        const int gw = bid * (NTHREADS / 32) + wid;     // 0..639
        #pragma unroll
        for (int pass = 0; pass < 2; pass++) {
            int p = gw + pass * (NBLOCKS * NTHREADS / 32);
            if (p < N_PROP) {
                const float* row = logits + p * NUM_CLASSES;
                float v0 = row[lane];
                float v1 = row[lane + 32];
                float v2 = (lane + 64 < NUM_CLASSES) ? row[lane + 64] : -INFINITY;
                float m = fmaxf(fmaxf(v0, v1), v2);
                #pragma unroll
                for (int o = 16; o > 0; o >>= 1) m = fmaxf(m, __shfl_xor_sync(0xffffffffu, m, o));
                float s = expf(v0 - m) + expf(v1 - m);
                if (lane + 64 < NUM_CLASSES) s += expf(v2 - m);
                #pragma unroll
                for (int o = 16; o > 0; o >>= 1) s += __shfl_xor_sync(0xffffffffu, s, o);
                if (lane == 0) g_lse[p] = m + logf(s);
            }
        }
    }
    grid_sync();

    // ================= Phase B: per-class decode + sort + NMS =================
    {
        const int c = bid + 1;               // foreground class 1..80
        if (tid == 0) sm.nms.cnt = 0;
        __syncthreads();

        const float W = load_dim(iw_p) - 1.0f;
        const float H = load_dim(ih_p) - 1.0f;

        for (int p = tid; p < N_PROP; p += NTHREADS) {
            float sc = expf(logits[p * NUM_CLASSES + c] - g_lse[p]);
            if (sc > SCORE_THRESH) {
                float x1 = pboxes[p * 4 + 0], y1 = pboxes[p * 4 + 1];
                float x2 = pboxes[p * 4 + 2], y2 = pboxes[p * 4 + 3];
                float w  = x2 - x1 + 1.0f,  h  = y2 - y1 + 1.0f;
                float cx = x1 + 0.5f * w,   cy = y1 + 0.5f * h;
                const float* d = deltas + p * (NUM_CLASSES * 4) + c * 4;
                float dx = d[0] / 10.0f;
                float dy = d[1] / 10.0f;
                float dw = fminf(d[2] / 5.0f, BBOX_XFORM_CLIP);
                float dh = fminf(d[3] / 5.0f, BBOX_XFORM_CLIP);
                float pcx = dx * w + cx, pcy = dy * h + cy;
                float pw  = expf(dw) * w, ph = expf(dh) * h;
                float bx1 = fminf(fmaxf(pcx - 0.5f * pw, 0.0f), W);
                float by1 = fminf(fmaxf(pcy - 0.5f * ph, 0.0f), H);
                float bx2 = fminf(fmaxf(pcx + 0.5f * pw - 1.0f, 0.0f), W);
                float by2 = fminf(fmaxf(pcy + 0.5f * ph - 1.0f, 0.0f), H);
                int slot = atomicAdd(&sm.nms.cnt, 1);
                sm.nms.key[slot] = ((u64)__float_as_uint(sc) << 32) | (u32)(~p);
                sm.nms.box[slot] = make_float4(bx1, by1, bx2, by2);
            }
        }
        __syncthreads();
        const int M = sm.nms.cnt;

        if (M > 0) {
            // bitonic sort descending on packed u64 (ties -> smaller p first)
            int P = 1;
            while (P < M) P <<= 1;
            for (int i = M + tid; i < P; i += NTHREADS) sm.nms.key[i] = 0ULL;
            __syncthreads();

            for (int k = 2; k <= P; k <<= 1) {
                for (int j = k >> 1; j > 0; j >>= 1) {
                    for (int i = tid; i < P; i += NTHREADS) {
                        int ixj = i ^ j;
                        if (ixj > i) {
                            u64 a = sm.nms.key[i], b = sm.nms.key[ixj];
                            bool up = ((i & k) == 0);
                            if (up ? (a < b) : (a > b)) {
                                sm.nms.key[i] = b; sm.nms.key[ixj] = a;
                                float4 tb = sm.nms.box[i];
                                sm.nms.box[i] = sm.nms.box[ixj];
                                sm.nms.box[ixj] = tb;
                            }
                        }
                    }
                    __syncthreads();
                }
            }

            const bool shpath = (M <= MROW_SH);
            const int mwords = shpath ? MWORDS_SH : MWORDS;
            u32* mask = shpath ? sm.nms.masksh : &g_mask[bid * MROW * MWORDS];
            const int Wd = (M + 31) >> 5;

            // build suppression rows (row i: bits j>i with IoU>thresh)
            for (int i = tid; i < M; i += NTHREADS) {
                u32* row = &mask[i * mwords];
                for (int w = 0; w < Wd; w++) row[w] = 0;
                float4 bi = sm.nms.box[i];
                float ai = (bi.z - bi.x + 1.0f) * (bi.w - bi.y + 1.0f);
                u32 cur = 0; int curw = (i + 1) >> 5;
                for (int j = i + 1; j < M; j++) {
                    int w = j >> 5;
                    if (w != curw) {
                        if (cur) row[curw] = cur;
                        cur = 0; curw = w;
                    }
                    float4 bj = sm.nms.box[j];
                    float lx = fmaxf(bi.x, bj.x), ly = fmaxf(bi.y, bj.y);
                    float rx = fminf(bi.z, bj.z), ry = fminf(bi.w, bj.w);
                    float iw = fmaxf(rx - lx + 1.0f, 0.0f);
                    float ih = fmaxf(ry - ly + 1.0f, 0.0f);
                    float inter = iw * ih;
                    float aj = (bj.z - bj.x + 1.0f) * (bj.w - bj.y + 1.0f);
                    if (inter / (ai + aj - inter) > NMS_THRESH) cur |= 1u << (j & 31);
                }
                if (cur) row[curw] = cur;
            }
            __syncthreads();

            // greedy resolve: warp 0, lane = mask word
            if (tid < 32) {
                u32 kw = (lane < Wd) ? 0xffffffffu : 0u;
                int rem = M & 31;
                if (rem && lane == Wd - 1) kw = (1u << rem) - 1u;
                for (int i = 0; i < M; i++) {
                    u32 srcw = __shfl_sync(0xffffffffu, kw, i >> 5);
                    if ((srcw >> (i & 31)) & 1u) {
                        u32 rw = (lane < Wd) ? mask[i * mwords + lane] : 0u;
                        kw &= ~rw;
                    }
                }
                if (lane < Wd) sm.nms.keepw[lane] = kw;
            }
            __syncthreads();

            // append survivors
            for (int j = tid; j < M; j += NTHREADS) {
                if ((sm.nms.keepw[j >> 5] >> (j & 31)) & 1u) {
                    int key = bid * N_PROP + j;      // reference flat index
                    int pos = atomicAdd(&g_count, 1);
                    g_cscore[pos] = __uint_as_float((u32)(sm.nms.key[j] >> 32));
                    g_ckey[pos]   = key;
                    g_boxkey[key] = sm.nms.box[j];
                }
            }
        }
    }
    grid_sync();

    // ================= Phase C: block 0 top-100 =================
    if (bid != 0) return;

    const int K = g_count;
    const int target = (K < DET_PER_IMG) ? K : DET_PER_IMG;

    for (int i = tid; i < NBINS; i += NTHREADS) sm.topk.hist[i] = 0;
    if (tid == 0) { sm.topk.bstar = 0; sm.topk.cnt = 0; }
    __syncthreads();

    for (int i = tid; i < K; i += NTHREADS)
        atomicAdd(&sm.topk.hist[score_bin(__float_as_uint(g_cscore[i]))], 1);
    __syncthreads();

    // suffix scan over 256 chunks of 16 bins
    const int CH = NBINS / NTHREADS;        // 16
    const int base = tid * CH;
    int cs[16];
    int sum = 0;
    #pragma unroll
    for (int t = 0; t < CH; t++) { cs[t] = sm.topk.hist[base + t]; sum += cs[t]; }
    sm.topk.part[tid] = sum;
    __syncthreads();
    for (int off = 1; off < NTHREADS; off <<= 1) {
        int add = (tid + off < NTHREADS) ? sm.topk.part[tid + off] : 0;
        __syncthreads();
        sm.topk.part[tid] += add;
        __syncthreads();
    }
    {
        int suf = (tid < NTHREADS - 1) ? sm.topk.part[tid + 1] : 0;
        #pragma unroll
        for (int t = CH - 1; t >= 0; t--) {
            suf += cs[t];
            if (suf >= target) { atomicMax(&sm.topk.bstar, base + t); break; }
        }
    }
    __syncthreads();
    const int bstar = sm.topk.bstar;

    for (int i = tid; i < K; i += NTHREADS) {
        u32 sb = __float_as_uint(g_cscore[i]);
        if (score_bin(sb) >= bstar) {
            int pos = atomicAdd(&sm.topk.cnt, 1);
            if (pos < TOPK_CAP)
                sm.topk.buf[pos] = ((u64)sb << 32) | (u32)(~g_ckey[i]);
        }
    }
    __syncthreads();
    const int C = sm.topk.cnt;

    if (C <= TOPK_CAP) {
        int P2 = 128;
        while (P2 < C) P2 <<= 1;
        for (int i = C + tid; i < P2; i += NTHREADS) sm.topk.buf[i] = 0ULL;
        __syncthreads();

        for (int k = 2; k <= P2; k <<= 1) {
            for (int j = k >> 1; j > 0; j >>= 1) {
                for (int i = tid; i < P2; i += NTHREADS) {
                    int ixj = i ^ j;
                    if (ixj > i) {
                        u64 a = sm.topk.buf[i], b = sm.topk.buf[ixj];
                        bool up = ((i & k) == 0);
                        if (up ? (a < b) : (a > b)) { sm.topk.buf[i] = b; sm.topk.buf[ixj] = a; }
                    }
                }
                __syncthreads();
            }
        }

        for (int r = tid; r < DET_PER_IMG; r += NTHREADS) {
            if (r < C) {
                u64 v = sm.topk.buf[r];
                int key = (int)(~(u32)v);
                float4 b = g_boxkey[key];
                out[r] = __uint_as_float((u32)(v >> 32));
                out[DET_PER_IMG + r * 4 + 0] = b.x;
                out[DET_PER_IMG + r * 4 + 1] = b.y;
                out[DET_PER_IMG + r * 4 + 2] = b.z;
                out[DET_PER_IMG + r * 4 + 3] = b.w;
                out[DET_PER_IMG * 5 + r] = (float)(key / N_PROP + 1);
            } else {
                out[r] = 0.0f;
                out[DET_PER_IMG + r * 4 + 0] = 0.0f;
                out[DET_PER_IMG + r * 4 + 1] = 0.0f;
                out[DET_PER_IMG + r * 4 + 2] = 0.0f;
                out[DET_PER_IMG + r * 4 + 3] = 0.0f;
                out[DET_PER_IMG * 5 + r] = 0.0f;
            }
        }
        return;
    }

    // -------- fallback: repeated global argmax (C > TOPK_CAP, pathological) ------
    u64* r_v = sm.topk.buf;                 // alias
    int* r_i = (int*)(sm.topk.buf + NTHREADS);
    __syncthreads();
    for (int r = 0; r < DET_PER_IMG; r++) {
        u64 bv = 0ULL; int bi = -1;
        for (int i = tid; i < K; i += NTHREADS) {
            u32 sb = __float_as_uint(g_cscore[i]);
            u64 v = ((u64)sb << 32) | (u32)(~g_ckey[i]);
            if (v > bv) { bv = v; bi = i; }
        }
        r_v[tid] = bv; r_i[tid] = bi;
        __syncthreads();
        for (int off = NTHREADS >> 1; off > 0; off >>= 1) {
            if (tid < off) {
                if (r_v[tid + off] > r_v[tid]) { r_v[tid] = r_v[tid + off]; r_i[tid] = r_i[tid + off]; }
            }
            __syncthreads();
        }
        if (tid == 0) {
            int idx = r_i[0];
            u64 v = r_v[0];
            int key = (int)(~(u32)v);
            float4 b = g_boxkey[key];
            out[r] = __uint_as_float((u32)(v >> 32));
            out[DET_PER_IMG + r * 4 + 0] = b.x;
            out[DET_PER_IMG + r * 4 + 1] = b.y;
            out[DET_PER_IMG + r * 4 + 2] = b.z;
            out[DET_PER_IMG + r * 4 + 3] = b.w;
            out[DET_PER_IMG * 5 + r] = (float)(key / N_PROP + 1);
            g_cscore[idx] = 0.0f;
        }
        __syncthreads();
    }
}

extern "C" void kernel_launch(void* const* d_in, const int* in_sizes, int n_in,
                              void* d_out, int out_size) {
    const float* logits = (const float*)d_in[0];   // [1000, 81]
    const float* deltas = (const float*)d_in[1];   // [1000, 324]
    const float* pboxes = (const float*)d_in[2];   // [1000, 4]
    const int*   ih     = (const int*)d_in[3];     // scalar
    const int*   iw     = (const int*)d_in[4];     // scalar

    fused_kernel<<<NBLOCKS, NTHREADS>>>(logits, deltas, pboxes, ih, iw, (float*)d_out);
}